// round 10
// baseline (speedup 1.0000x reference)
#include <cuda_runtime.h>
#include <cuda_fp16.h>
#include <cstdint>

#define BB   16
#define CI   64
#define CO   64
#define HHH  128
#define WWW  128
#define NN   8

#define SXU 17408            // u32: x full tile, 4 ri x 32 ci2 x 136 (half2)
#define WBU 4608             // u32 per W ci-block: 9 t x 4 mt x 32 lanes x 4
#define SMEM_BYTES ((SXU + 2 * WBU) * 4)   // 106,496

// ---------------------------------------------------------------------------
// Device scratch (no allocation allowed)
// ---------------------------------------------------------------------------
__device__ float g_beff[BB * CO];
// fragment-packed fp16 filters: [b][cb=4][t=9][mt=4][lane=32][4 regs] (half2)
__device__ uint32_t g_wefft[BB * 4 * 9 * 4 * 32 * 4];

// ---------------------------------------------------------------------------
// helpers
// ---------------------------------------------------------------------------
__device__ __forceinline__ uint32_t smem_u32(const void* p) {
    uint32_t a;
    asm("{ .reg .u64 t; cvta.to.shared.u64 t, %1; cvt.u32.u64 %0, t; }"
        : "=r"(a) : "l"(p));
    return a;
}
__device__ __forceinline__ void cpa16(uint32_t dst, const void* src) {
    asm volatile("cp.async.cg.shared.global [%0], [%1], 16;"
                 :: "r"(dst), "l"(src) : "memory");
}
__device__ __forceinline__ uint32_t h2pack(float lo, float hi) {
    uint32_t r;
    asm("cvt.rn.f16x2.f32 %0, %2, %1;" : "=r"(r) : "f"(lo), "f"(hi));
    return r;
}
__device__ __forceinline__ void mma16(float* d, const uint32_t* a, uint32_t b0, uint32_t b1) {
    asm volatile(
        "mma.sync.aligned.m16n8k16.row.col.f32.f16.f16.f32 "
        "{%0,%1,%2,%3}, {%4,%5,%6,%7}, {%8,%9}, {%0,%1,%2,%3};"
        : "+f"(d[0]), "+f"(d[1]), "+f"(d[2]), "+f"(d[3])
        : "r"(a[0]), "r"(a[1]), "r"(a[2]), "r"(a[3]), "r"(b0), "r"(b1));
}

// ---------------------------------------------------------------------------
// Kernel 1: effective filters, FRAGMENT-PACKED fp16 + bias. Warp-coalesced.
// warp task = blockIdx.x*8 + warpid in [0,128): co = task>>1, ci = (task&1)*32+lane.
// ---------------------------------------------------------------------------
__global__ void k_weff(const float* __restrict__ filt_w,
                       const float* __restrict__ cond,
                       const float* __restrict__ sel_w,
                       const float* __restrict__ sel_b,
                       const float* __restrict__ filt_b) {
    __shared__ float sw[NN];
    int b = blockIdx.y;
    int tid = threadIdx.x;
    int lane = tid & 31;
    int warp = tid >> 5;

    if (tid < 32) {
        int n = lane & 7;
        float logit = sel_b[n];
        #pragma unroll 8
        for (int k = 0; k < CI; k++)
            logit += cond[b * CI + k] * sel_w[n * CI + k];
        float m = logit;
        #pragma unroll
        for (int o = 4; o; o >>= 1) m = fmaxf(m, __shfl_xor_sync(0xffffffffu, m, o));
        float e = __expf(logit - m);
        float s = e;
        #pragma unroll
        for (int o = 4; o; o >>= 1) s += __shfl_xor_sync(0xffffffffu, s, o);
        if (lane < 8) sw[lane] = e / s;
    }
    __syncthreads();

    float w[NN];
    #pragma unroll
    for (int n = 0; n < NN; n++) w[n] = sw[n];

    int task = blockIdx.x * 8 + warp;      // 0..127
    int co  = task >> 1;
    int ci  = (task & 1) * 32 + lane;

    float acc[9];
    #pragma unroll
    for (int t = 0; t < 9; t++) acc[t] = 0.f;
    #pragma unroll
    for (int n = 0; n < NN; n++) {
        const float* fp = filt_w + ((size_t)(n * CO + co) * CI + ci) * 9;
        #pragma unroll
        for (int t = 0; t < 9; t++) acc[t] += w[n] * __ldg(fp + t);
    }

    uint32_t* outb = g_wefft + (size_t)b * 18432;
    int cq = ci & 15;
    int cb = ci >> 4;
    int lq = (cq & 7) >> 1;
    int e1 = cq >> 3;
    int mt = co >> 4;
    int lr = (co & 15) & 7;
    int e0 = (co & 15) >> 3;
    int fl = lr * 4 + lq;
    #pragma unroll
    for (int t = 0; t < 9; t++) {
        float hi = __shfl_down_sync(0xffffffffu, acc[t], 1);
        if (!(lane & 1)) {
            int idx = ((cb * 9 + t) * 4 + mt) * 128 + fl * 4 + (e1 * 2 + e0);
            outb[idx] = h2pack(acc[t], hi);
        }
    }

    if (blockIdx.x == 0 && tid < CO) {
        float sb = 0.f;
        #pragma unroll
        for (int n = 0; n < NN; n++) sb += w[n] * filt_b[n * CO + tid];
        g_beff[b * CO + tid] = sb;
    }
}

// ---------------------------------------------------------------------------
// Kernel 2: fp16 mma.sync conv. CTA = (h-pair, batch). 256 threads, 8 warps.
// x tile (4 ri x 64 ci, fp16 half2) loaded ONCE in the prologue; W double-
// buffered via cp.async. Loop body: pure LDS + MMA + one async W issue.
// x smem: [ri=4][ci2=32][136] half2 (ci even in .lo); halo at col idx 3/132.
// ---------------------------------------------------------------------------
__global__ __launch_bounds__(256, 2) void k_conv(const float* __restrict__ x,
                                                 float* __restrict__ out) {
    extern __shared__ uint32_t smu[];
    uint32_t* SX = smu;               // [SXU]
    uint32_t* SW = smu + SXU;         // [2][WBU]
    uint32_t sw_u = smem_u32(SW);

    int tid  = threadIdx.x;
    int warp = tid >> 5;
    int lane = tid & 31;
    int lq = lane & 3, lr = lane >> 2;
    int hl = warp >> 2;               // h row within pair
    int colb = (warp & 3) * 32;       // col quarter
    int h0 = blockIdx.x * 2;
    int b  = blockIdx.y;

    const float* xb  = x + (size_t)b * CI * HHH * WWW;
    const uint32_t* wbg = g_wefft + (size_t)b * 18432;

    // W blocks 0 and 1 -> buffers 0 and 1 (two commit groups)
    #pragma unroll
    for (int cb = 0; cb < 2; cb++) {
        #pragma unroll
        for (int k = 0; k < 5; k++) {
            int c = tid + 256 * k;
            if (c < 1152)
                cpa16(sw_u + (cb * WBU + c * 4) * 4,
                      wbg + (size_t)cb * 4608 + c * 4);
        }
        asm volatile("cp.async.commit_group;" ::: "memory");
    }

    // halo zero columns: 2 sides x 4 ri x 32 ci2 = 256 = one store per thread
    {
        int sd = tid & 1, idx = tid >> 1;
        int ci2 = idx & 31, ri = idx >> 5;
        SX[ri * 4352 + ci2 * 136 + (sd ? 132 : 3)] = 0u;
    }

    // full x tile: 4096 uint4 chunks = 16 per thread (LDG.128 pair -> cvt -> STS.128)
    #pragma unroll 4
    for (int k = 0; k < 16; k++) {
        int chunk = tid + 256 * k;
        int c4 = chunk & 31, ci2 = (chunk >> 5) & 31, ri = chunk >> 10;
        int gh = h0 - 1 + ri;
        float4 va = make_float4(0.f, 0.f, 0.f, 0.f), vb = va;
        if ((unsigned)gh < 128u) {
            const float* p = xb + ((size_t)(2 * ci2) * HHH + gh) * WWW + c4 * 4;
            va = __ldg((const float4*)p);
            vb = __ldg((const float4*)(p + HHH * WWW));
        }
        uint4 r;
        r.x = h2pack(va.x, vb.x);
        r.y = h2pack(va.y, vb.y);
        r.z = h2pack(va.z, vb.z);
        r.w = h2pack(va.w, vb.w);
        *(uint4*)(SX + ri * 4352 + ci2 * 136 + 4 + c4 * 4) = r;
    }

    float d[4][4][4];
    #pragma unroll
    for (int mt = 0; mt < 4; mt++)
        #pragma unroll
        for (int nt = 0; nt < 4; nt++)
            #pragma unroll
            for (int e = 0; e < 4; e++) d[mt][nt][e] = 0.f;

    asm volatile("cp.async.wait_group 1;" ::: "memory");   // W0 ready
    __syncthreads();

    int xoff = colb + 3 + lr;

    #pragma unroll 1
    for (int cb = 0; cb < 4; cb++) {
        const uint4* bw4 = (const uint4*)(SW + (cb & 1) * WBU);
        const uint32_t* bx = SX + (cb * 8 + lq) * 136 + xoff;

        #pragma unroll
        for (int kh = 0; kh < 3; kh++) {
            int ri = hl + kh;
            #pragma unroll
            for (int kw = 0; kw < 3; kw++) {
                int t = kh * 3 + kw;
                uint32_t a[4][4];
                #pragma unroll
                for (int mt = 0; mt < 4; mt++) {
                    uint4 v = bw4[(t * 4 + mt) * 32 + lane];
                    a[mt][0] = v.x; a[mt][1] = v.y; a[mt][2] = v.z; a[mt][3] = v.w;
                }
                const uint32_t* xp = bx + ri * 4352 + kw;
                #pragma unroll
                for (int nt = 0; nt < 4; nt++) {
                    uint32_t b0 = xp[nt * 8];              // ci2 = cb*8 + lq
                    uint32_t b1 = xp[4 * 136 + nt * 8];    // ci2 = cb*8 + lq + 4
                    #pragma unroll
                    for (int mt = 0; mt < 4; mt++)
                        mma16(d[mt][nt], a[mt], b0, b1);
                }
            }
        }

        if (cb < 3) {
            __syncthreads();                               // release buffer cb&1
            if (cb < 2) {                                  // W(cb+2) -> buffer cb&1
                #pragma unroll
                for (int k = 0; k < 5; k++) {
                    int c = tid + 256 * k;
                    if (c < 1152)
                        cpa16(sw_u + ((cb & 1) * WBU + c * 4) * 4,
                              wbg + (size_t)(cb + 2) * 4608 + c * 4);
                }
                asm volatile("cp.async.commit_group;" ::: "memory");
                asm volatile("cp.async.wait_group 1;" ::: "memory");
            } else {
                asm volatile("cp.async.wait_group 0;" ::: "memory");
            }
            __syncthreads();                               // publish W(cb+1)
        }
    }

    // epilogue: bias + store
    int h = h0 + hl;
    #pragma unroll
    for (int mt = 0; mt < 4; mt++) {
        int co = mt * 16 + lr;
        float bz0 = g_beff[b * CO + co];
        float bz1 = g_beff[b * CO + co + 8];
        float* r0 = out + (((size_t)(b * CO + co) * HHH + h) * WWW);
        float* r1 = out + (((size_t)(b * CO + co + 8) * HHH + h) * WWW);
        #pragma unroll
        for (int nt = 0; nt < 4; nt++) {
            int col = colb + nt * 8 + 2 * lq;
            *(float2*)(r0 + col) = make_float2(d[mt][nt][0] + bz0, d[mt][nt][1] + bz0);
            *(float2*)(r1 + col) = make_float2(d[mt][nt][2] + bz1, d[mt][nt][3] + bz1);
        }
    }
}

// ---------------------------------------------------------------------------
extern "C" void kernel_launch(void* const* d_in, const int* in_sizes, int n_in,
                              void* d_out, int out_size) {
    const float* x      = (const float*)d_in[0];   // [16,64,128,128]
    const float* cond   = (const float*)d_in[1];   // [16,64]
    const float* filt_w = (const float*)d_in[2];   // [8,64,64,3,3]
    const float* filt_b = (const float*)d_in[3];   // [8,64]
    const float* sel_w  = (const float*)d_in[4];   // [8,64]
    const float* sel_b  = (const float*)d_in[5];   // [8]
    float* out = (float*)d_out;                    // [16,64,128,128]

    cudaFuncSetAttribute(k_conv, cudaFuncAttributeMaxDynamicSharedMemorySize, SMEM_BYTES);

    dim3 g1(16, BB);                               // 128 warp-tasks / 8 per block
    k_weff<<<g1, 256>>>(filt_w, cond, sel_w, sel_b, filt_b);

    dim3 g2(HHH / 2, BB);                          // 64 h-pairs x 16 batches
    k_conv<<<g2, 256, SMEM_BYTES>>>(x, out);
}

// round 11
// speedup vs baseline: 1.5425x; 1.5425x over previous
#include <cuda_runtime.h>
#include <cuda_fp16.h>
#include <cstdint>

#define BB   16
#define CI   64
#define CO   64
#define HHH  128
#define WWW  128
#define NN   8

#define XBU 4352             // uint32 per x buffer: 4 ri x 8 ci2 x 136 (half2)
#define WBU 4608             // uint32 per W buffer: 9 t x 4 mt x 32 lanes x 4
#define SMEM_BYTES (2 * (XBU + WBU) * 4)   // 71,680  (<=72KB: keeps L1D large)

// ---------------------------------------------------------------------------
// Device scratch (no allocation allowed)
// ---------------------------------------------------------------------------
__device__ float g_beff[BB * CO];
// fragment-packed fp16 filters: [b][cb=4][t=9][mt=4][lane=32][4 regs] (half2)
__device__ uint32_t g_wefft[BB * 4 * 9 * 4 * 32 * 4];

// ---------------------------------------------------------------------------
// helpers
// ---------------------------------------------------------------------------
__device__ __forceinline__ uint32_t smem_u32(const void* p) {
    uint32_t a;
    asm("{ .reg .u64 t; cvta.to.shared.u64 t, %1; cvt.u32.u64 %0, t; }"
        : "=r"(a) : "l"(p));
    return a;
}
__device__ __forceinline__ void cpa16(uint32_t dst, const void* src) {
    asm volatile("cp.async.cg.shared.global [%0], [%1], 16;"
                 :: "r"(dst), "l"(src) : "memory");
}
__device__ __forceinline__ uint32_t h2pack(float lo, float hi) {
    uint32_t r;
    asm("cvt.rn.f16x2.f32 %0, %2, %1;" : "=r"(r) : "f"(lo), "f"(hi));
    return r;
}
__device__ __forceinline__ void mma16(float* d, const uint32_t* a, uint32_t b0, uint32_t b1) {
    asm volatile(
        "mma.sync.aligned.m16n8k16.row.col.f32.f16.f16.f32 "
        "{%0,%1,%2,%3}, {%4,%5,%6,%7}, {%8,%9}, {%0,%1,%2,%3};"
        : "+f"(d[0]), "+f"(d[1]), "+f"(d[2]), "+f"(d[3])
        : "r"(a[0]), "r"(a[1]), "r"(a[2]), "r"(a[3]), "r"(b0), "r"(b1));
}

// ---------------------------------------------------------------------------
// Kernel 1: effective filters, FRAGMENT-PACKED fp16 + bias. Warp-coalesced
// (round-9 version: per-warp contiguous filt_w spans, shfl lane pairing).
// warp task = blockIdx.x*8 + warpid in [0,128): co = task>>1, ci = (task&1)*32+lane.
// ---------------------------------------------------------------------------
__global__ void k_weff(const float* __restrict__ filt_w,
                       const float* __restrict__ cond,
                       const float* __restrict__ sel_w,
                       const float* __restrict__ sel_b,
                       const float* __restrict__ filt_b) {
    __shared__ float sw[NN];
    int b = blockIdx.y;
    int tid = threadIdx.x;
    int lane = tid & 31;
    int warp = tid >> 5;

    if (tid < 32) {
        int n = lane & 7;
        float logit = sel_b[n];
        #pragma unroll 8
        for (int k = 0; k < CI; k++)
            logit += cond[b * CI + k] * sel_w[n * CI + k];
        float m = logit;
        #pragma unroll
        for (int o = 4; o; o >>= 1) m = fmaxf(m, __shfl_xor_sync(0xffffffffu, m, o));
        float e = __expf(logit - m);
        float s = e;
        #pragma unroll
        for (int o = 4; o; o >>= 1) s += __shfl_xor_sync(0xffffffffu, s, o);
        if (lane < 8) sw[lane] = e / s;
    }
    __syncthreads();

    float w[NN];
    #pragma unroll
    for (int n = 0; n < NN; n++) w[n] = sw[n];

    int task = blockIdx.x * 8 + warp;      // 0..127
    int co  = task >> 1;
    int ci  = (task & 1) * 32 + lane;

    float acc[9];
    #pragma unroll
    for (int t = 0; t < 9; t++) acc[t] = 0.f;
    #pragma unroll
    for (int n = 0; n < NN; n++) {
        const float* fp = filt_w + ((size_t)(n * CO + co) * CI + ci) * 9;
        #pragma unroll
        for (int t = 0; t < 9; t++) acc[t] += w[n] * __ldg(fp + t);
    }

    uint32_t* outb = g_wefft + (size_t)b * 18432;
    int cq = ci & 15;
    int cb = ci >> 4;
    int lq = (cq & 7) >> 1;
    int e1 = cq >> 3;
    int mt = co >> 4;
    int lr = (co & 15) & 7;
    int e0 = (co & 15) >> 3;
    int fl = lr * 4 + lq;
    #pragma unroll
    for (int t = 0; t < 9; t++) {
        float hi = __shfl_down_sync(0xffffffffu, acc[t], 1);
        if (!(lane & 1)) {
            int idx = ((cb * 9 + t) * 4 + mt) * 128 + fl * 4 + (e1 * 2 + e0);
            outb[idx] = h2pack(acc[t], hi);
        }
    }

    if (blockIdx.x == 0 && tid < CO) {
        float sb = 0.f;
        #pragma unroll
        for (int n = 0; n < NN; n++) sb += w[n] * filt_b[n * CO + tid];
        g_beff[b * CO + tid] = sb;
    }
}

// ---------------------------------------------------------------------------
// Kernel 2: fp16 mma.sync conv — ROUND-8 structure (measured 60.2us).
// CTA = (h-pair, batch). 256 threads, 8 warps.
// Warp: M=64co x N=32px (one h row, 32-col quarter). 4 ci-blocks of 16.
// smem x: [2][4 ri][8 ci2][136] half2 (ci even in .lo), halo cols at 3/132.
// x rounded to fp16 in registers during staging; W double-buffered cp.async.
// ---------------------------------------------------------------------------
__global__ __launch_bounds__(256, 2) void k_conv(const float* __restrict__ x,
                                                 float* __restrict__ out) {
    extern __shared__ uint32_t smu[];
    uint32_t* SX = smu;               // [2][XBU]
    uint32_t* SW = smu + 2 * XBU;     // [2][WBU]
    uint32_t sw_u = smem_u32(SW);

    int tid  = threadIdx.x;
    int warp = tid >> 5;
    int lane = tid & 31;
    int lq = lane & 3, lr = lane >> 2;
    int hl = warp >> 2;               // h row within pair
    int colb = (warp & 3) * 32;       // col quarter
    int h0 = blockIdx.x * 2;
    int b  = blockIdx.y;

    // halo zero columns (col -1 at idx 3, col 128 at idx 132), both buffers
    if (tid < 128) {
        int sd = tid & 1, ci2 = (tid >> 1) & 7, ri = (tid >> 4) & 3, bf = tid >> 6;
        SX[bf * XBU + ri * 1088 + ci2 * 136 + (sd ? 132 : 3)] = 0u;
    }

    // per-thread x staging geometry
    int c4 = tid & 31, ci2s = (tid >> 5) & 7;
    const float* xb  = x + (size_t)b * CI * HHH * WWW;
    const uint32_t* wbg = g_wefft + (size_t)b * 18432;

    uint4 rx[4];
    #define LDGX(cb)                                                            \
    {                                                                           \
        _Pragma("unroll")                                                       \
        for (int k = 0; k < 4; k++) {                                           \
            int gh = h0 - 1 + k;                                                \
            float4 va = make_float4(0.f, 0.f, 0.f, 0.f), vb = va;               \
            if ((unsigned)gh < 128u) {                                          \
                const float* p = xb + ((size_t)((cb) * 16 + 2 * ci2s) * HHH + gh) * WWW + c4 * 4; \
                va = __ldg((const float4*)p);                                   \
                vb = __ldg((const float4*)(p + HHH * WWW));                     \
            }                                                                   \
            rx[k].x = h2pack(va.x, vb.x);                                       \
            rx[k].y = h2pack(va.y, vb.y);                                       \
            rx[k].z = h2pack(va.z, vb.z);                                       \
            rx[k].w = h2pack(va.w, vb.w);                                       \
        }                                                                       \
    }
    #define STSX(bf)                                                            \
    {                                                                           \
        _Pragma("unroll")                                                       \
        for (int k = 0; k < 4; k++)                                             \
            *(uint4*)(SX + (bf) * XBU + k * 1088 + ci2s * 136 + 4 + c4 * 4) = rx[k]; \
    }
    #define STGW(cb, bf)                                                        \
    {                                                                           \
        _Pragma("unroll")                                                       \
        for (int k = 0; k < 5; k++) {                                           \
            int c = tid + 256 * k;                                              \
            if (c < 1152)                                                       \
                cpa16(sw_u + ((bf) * WBU + c * 4) * 4,                          \
                      wbg + (size_t)(cb) * 4608 + c * 4);                       \
        }                                                                       \
        asm volatile("cp.async.commit_group;" ::: "memory");                    \
    }

    float d[4][4][4];
    #pragma unroll
    for (int mt = 0; mt < 4; mt++)
        #pragma unroll
        for (int nt = 0; nt < 4; nt++)
            #pragma unroll
            for (int e = 0; e < 4; e++) d[mt][nt][e] = 0.f;

    // prologue: fill buffer 0
    LDGX(0);
    STGW(0, 0);
    STSX(0);
    asm volatile("cp.async.wait_group 0;" ::: "memory");
    __syncthreads();

    int xoff = lq * 136 + colb + 3 + lr;   // ci2 = lq, col = colb+lr (+kw, +nt*8)

    #pragma unroll 1
    for (int cb = 0; cb < 4; cb++) {
        int buf = cb & 1;
        if (cb < 3) {
            LDGX(cb + 1);
            STGW(cb + 1, buf ^ 1);
        }

        const uint32_t* bxu = SX + buf * XBU;
        const uint4*    bw4 = (const uint4*)(SW + buf * WBU);

        #pragma unroll
        for (int kh = 0; kh < 3; kh++) {
            int ri = hl + kh;
            #pragma unroll
            for (int kw = 0; kw < 3; kw++) {
                int t = kh * 3 + kw;
                uint32_t a[4][4];
                #pragma unroll
                for (int mt = 0; mt < 4; mt++) {
                    uint4 v = bw4[(t * 4 + mt) * 32 + lane];
                    a[mt][0] = v.x; a[mt][1] = v.y; a[mt][2] = v.z; a[mt][3] = v.w;
                }
                const uint32_t* xp = bxu + ri * 1088 + xoff + kw;
                #pragma unroll
                for (int nt = 0; nt < 4; nt++) {
                    uint32_t b0 = xp[nt * 8];              // ci2 = lq
                    uint32_t b1 = xp[4 * 136 + nt * 8];    // ci2 = lq + 4
                    #pragma unroll
                    for (int mt = 0; mt < 4; mt++)
                        mma16(d[mt][nt], a[mt], b0, b1);
                }
            }
        }

        if (cb < 3) {
            STSX(buf ^ 1);
            asm volatile("cp.async.wait_group 0;" ::: "memory");
        }
        __syncthreads();
    }

    // epilogue: bias + store
    int h = h0 + hl;
    #pragma unroll
    for (int mt = 0; mt < 4; mt++) {
        int co = mt * 16 + lr;
        float bz0 = g_beff[b * CO + co];
        float bz1 = g_beff[b * CO + co + 8];
        float* r0 = out + (((size_t)(b * CO + co) * HHH + h) * WWW);
        float* r1 = out + (((size_t)(b * CO + co + 8) * HHH + h) * WWW);
        #pragma unroll
        for (int nt = 0; nt < 4; nt++) {
            int col = colb + nt * 8 + 2 * lq;
            *(float2*)(r0 + col) = make_float2(d[mt][nt][0] + bz0, d[mt][nt][1] + bz0);
            *(float2*)(r1 + col) = make_float2(d[mt][nt][2] + bz1, d[mt][nt][3] + bz1);
        }
    }
}

// ---------------------------------------------------------------------------
extern "C" void kernel_launch(void* const* d_in, const int* in_sizes, int n_in,
                              void* d_out, int out_size) {
    const float* x      = (const float*)d_in[0];   // [16,64,128,128]
    const float* cond   = (const float*)d_in[1];   // [16,64]
    const float* filt_w = (const float*)d_in[2];   // [8,64,64,3,3]
    const float* filt_b = (const float*)d_in[3];   // [8,64]
    const float* sel_w  = (const float*)d_in[4];   // [8,64]
    const float* sel_b  = (const float*)d_in[5];   // [8]
    float* out = (float*)d_out;                    // [16,64,128,128]

    cudaFuncSetAttribute(k_conv, cudaFuncAttributeMaxDynamicSharedMemorySize, SMEM_BYTES);

    dim3 g1(16, BB);                               // 128 warp-tasks / 8 per block
    k_weff<<<g1, 256>>>(filt_w, cond, sel_w, sel_b, filt_b);

    dim3 g2(HHH / 2, BB);                          // 64 h-pairs x 16 batches
    k_conv<<<g2, 256, SMEM_BYTES>>>(x, out);
}

// round 12
// speedup vs baseline: 1.5896x; 1.0305x over previous
#include <cuda_runtime.h>
#include <cuda_fp16.h>
#include <cstdint>

#define BB   16
#define CI   64
#define CO   64
#define HHH  128
#define WWW  128
#define NN   8

#define XBU 4352             // uint32 per x buffer: 4 ri x 8 ci2 x 136 (half2)
#define WBU 4608             // uint32 per W buffer: 9 t x 4 mt x 32 lanes x 4
#define SMEM_BYTES (2 * (XBU + WBU) * 4)   // 71,680  (<=72KB: keeps L1D large)
#define NTILES (64 * BB)     // 64 h-pairs x 16 batches

// ---------------------------------------------------------------------------
// Device scratch (no allocation allowed)
// ---------------------------------------------------------------------------
__device__ float g_beff[BB * CO];
// fragment-packed fp16 filters: [b][cb=4][t=9][mt=4][lane=32][4 regs] (half2)
__device__ uint32_t g_wefft[BB * 4 * 9 * 4 * 32 * 4];

// ---------------------------------------------------------------------------
// helpers
// ---------------------------------------------------------------------------
__device__ __forceinline__ uint32_t smem_u32(const void* p) {
    uint32_t a;
    asm("{ .reg .u64 t; cvta.to.shared.u64 t, %1; cvt.u32.u64 %0, t; }"
        : "=r"(a) : "l"(p));
    return a;
}
__device__ __forceinline__ void cpa16(uint32_t dst, const void* src) {
    asm volatile("cp.async.cg.shared.global [%0], [%1], 16;"
                 :: "r"(dst), "l"(src) : "memory");
}
__device__ __forceinline__ uint32_t h2pack(float lo, float hi) {
    uint32_t r;
    asm("cvt.rn.f16x2.f32 %0, %2, %1;" : "=r"(r) : "f"(lo), "f"(hi));
    return r;
}
__device__ __forceinline__ void mma16(float* d, const uint32_t* a, uint32_t b0, uint32_t b1) {
    asm volatile(
        "mma.sync.aligned.m16n8k16.row.col.f32.f16.f16.f32 "
        "{%0,%1,%2,%3}, {%4,%5,%6,%7}, {%8,%9}, {%0,%1,%2,%3};"
        : "+f"(d[0]), "+f"(d[1]), "+f"(d[2]), "+f"(d[3])
        : "r"(a[0]), "r"(a[1]), "r"(a[2]), "r"(a[3]), "r"(b0), "r"(b1));
}

// ---------------------------------------------------------------------------
// Kernel 1: effective filters, FRAGMENT-PACKED fp16 + bias. Warp-coalesced.
// warp task = blockIdx.x*8 + warpid in [0,128): co = task>>1, ci = (task&1)*32+lane.
// ---------------------------------------------------------------------------
__global__ void k_weff(const float* __restrict__ filt_w,
                       const float* __restrict__ cond,
                       const float* __restrict__ sel_w,
                       const float* __restrict__ sel_b,
                       const float* __restrict__ filt_b) {
    __shared__ float sw[NN];
    int b = blockIdx.y;
    int tid = threadIdx.x;
    int lane = tid & 31;
    int warp = tid >> 5;

    if (tid < 32) {
        int n = lane & 7;
        float logit = sel_b[n];
        #pragma unroll 8
        for (int k = 0; k < CI; k++)
            logit += cond[b * CI + k] * sel_w[n * CI + k];
        float m = logit;
        #pragma unroll
        for (int o = 4; o; o >>= 1) m = fmaxf(m, __shfl_xor_sync(0xffffffffu, m, o));
        float e = __expf(logit - m);
        float s = e;
        #pragma unroll
        for (int o = 4; o; o >>= 1) s += __shfl_xor_sync(0xffffffffu, s, o);
        if (lane < 8) sw[lane] = e / s;
    }
    __syncthreads();

    float w[NN];
    #pragma unroll
    for (int n = 0; n < NN; n++) w[n] = sw[n];

    int task = blockIdx.x * 8 + warp;      // 0..127
    int co  = task >> 1;
    int ci  = (task & 1) * 32 + lane;

    float acc[9];
    #pragma unroll
    for (int t = 0; t < 9; t++) acc[t] = 0.f;
    #pragma unroll
    for (int n = 0; n < NN; n++) {
        const float* fp = filt_w + ((size_t)(n * CO + co) * CI + ci) * 9;
        #pragma unroll
        for (int t = 0; t < 9; t++) acc[t] += w[n] * __ldg(fp + t);
    }

    uint32_t* outb = g_wefft + (size_t)b * 18432;
    int cq = ci & 15;
    int cb = ci >> 4;
    int lq = (cq & 7) >> 1;
    int e1 = cq >> 3;
    int mt = co >> 4;
    int lr = (co & 15) & 7;
    int e0 = (co & 15) >> 3;
    int fl = lr * 4 + lq;
    #pragma unroll
    for (int t = 0; t < 9; t++) {
        float hi = __shfl_down_sync(0xffffffffu, acc[t], 1);
        if (!(lane & 1)) {
            int idx = ((cb * 9 + t) * 4 + mt) * 128 + fl * 4 + (e1 * 2 + e0);
            outb[idx] = h2pack(acc[t], hi);
        }
    }

    if (blockIdx.x == 0 && tid < CO) {
        float sb = 0.f;
        #pragma unroll
        for (int n = 0; n < NN; n++) sb += w[n] * filt_b[n * CO + tid];
        g_beff[b * CO + tid] = sb;
    }
}

// ---------------------------------------------------------------------------
// Kernel 2: fp16 mma.sync conv — PERSISTENT CTAs over h-pair tiles.
// Tile = (h-pair, batch). 256 threads, 8 warps.
// Warp: M=64co x N=32px (one h row, 32-col quarter). 4 ci-blocks of 16.
// smem x: [2][4 ri][8 ci2][136] half2 (ci even in .lo), halo cols at 3/132.
// Tile->tile rolls with no extra barrier: last cb reads buffers 1, next
// prologue writes buffers 0, published by the prologue's own barrier.
// ---------------------------------------------------------------------------
__global__ __launch_bounds__(256, 2) void k_conv(const float* __restrict__ x,
                                                 float* __restrict__ out) {
    extern __shared__ uint32_t smu[];
    uint32_t* SX = smu;               // [2][XBU]
    uint32_t* SW = smu + 2 * XBU;     // [2][WBU]
    uint32_t sw_u = smem_u32(SW);

    int tid  = threadIdx.x;
    int warp = tid >> 5;
    int lane = tid & 31;
    int lq = lane & 3, lr = lane >> 2;
    int hl = warp >> 2;               // h row within pair
    int colb = (warp & 3) * 32;       // col quarter
    int c4 = tid & 31, ci2s = (tid >> 5) & 7;
    int xoff = lq * 136 + colb + 3 + lr;

    // halo zero columns (col -1 at idx 3, col 128 at idx 132), both buffers.
    // These slots are never overwritten (STSX covers idx 4..131) -> once only.
    if (tid < 128) {
        int sd = tid & 1, ci2 = (tid >> 1) & 7, ri = (tid >> 4) & 3, bf = tid >> 6;
        SX[bf * XBU + ri * 1088 + ci2 * 136 + (sd ? 132 : 3)] = 0u;
    }

    uint4 rx[4];
    #define LDGX(cb)                                                            \
    {                                                                           \
        _Pragma("unroll")                                                       \
        for (int k = 0; k < 4; k++) {                                           \
            int gh = h0 - 1 + k;                                                \
            float4 va = make_float4(0.f, 0.f, 0.f, 0.f), vb = va;               \
            if ((unsigned)gh < 128u) {                                          \
                const float* p = xb + ((size_t)((cb) * 16 + 2 * ci2s) * HHH + gh) * WWW + c4 * 4; \
                va = __ldg((const float4*)p);                                   \
                vb = __ldg((const float4*)(p + HHH * WWW));                     \
            }                                                                   \
            rx[k].x = h2pack(va.x, vb.x);                                       \
            rx[k].y = h2pack(va.y, vb.y);                                       \
            rx[k].z = h2pack(va.z, vb.z);                                       \
            rx[k].w = h2pack(va.w, vb.w);                                       \
        }                                                                       \
    }
    #define STSX(bf)                                                            \
    {                                                                           \
        _Pragma("unroll")                                                       \
        for (int k = 0; k < 4; k++)                                             \
            *(uint4*)(SX + (bf) * XBU + k * 1088 + ci2s * 136 + 4 + c4 * 4) = rx[k]; \
    }
    #define STGW(cb, bf)                                                        \
    {                                                                           \
        _Pragma("unroll")                                                       \
        for (int k = 0; k < 5; k++) {                                           \
            int c = tid + 256 * k;                                              \
            if (c < 1152)                                                       \
                cpa16(sw_u + ((bf) * WBU + c * 4) * 4,                          \
                      wbg + (size_t)(cb) * 4608 + c * 4);                       \
        }                                                                       \
        asm volatile("cp.async.commit_group;" ::: "memory");                    \
    }

    for (int tile = blockIdx.x; tile < NTILES; tile += gridDim.x) {
        int hp = tile & 63;
        int b  = tile >> 6;
        int h0 = hp * 2;
        const float* xb  = x + (size_t)b * CI * HHH * WWW;
        const uint32_t* wbg = g_wefft + (size_t)b * 18432;

        // accumulators initialized with bias
        float d[4][4][4];
        #pragma unroll
        for (int mt = 0; mt < 4; mt++) {
            float bz0 = g_beff[b * CO + mt * 16 + lr];
            float bz1 = g_beff[b * CO + mt * 16 + lr + 8];
            #pragma unroll
            for (int nt = 0; nt < 4; nt++) {
                d[mt][nt][0] = bz0; d[mt][nt][1] = bz0;
                d[mt][nt][2] = bz1; d[mt][nt][3] = bz1;
            }
        }

        // prologue: fill buffer 0
        LDGX(0);
        STGW(0, 0);
        STSX(0);
        asm volatile("cp.async.wait_group 0;" ::: "memory");
        __syncthreads();

        #pragma unroll 1
        for (int cb = 0; cb < 4; cb++) {
            int buf = cb & 1;
            if (cb < 3) {
                LDGX(cb + 1);
                STGW(cb + 1, buf ^ 1);
            }

            const uint32_t* bxu = SX + buf * XBU;
            const uint4*    bw4 = (const uint4*)(SW + buf * WBU);

            #pragma unroll
            for (int kh = 0; kh < 3; kh++) {
                int ri = hl + kh;
                #pragma unroll
                for (int kw = 0; kw < 3; kw++) {
                    int t = kh * 3 + kw;
                    uint32_t a[4][4];
                    #pragma unroll
                    for (int mt = 0; mt < 4; mt++) {
                        uint4 v = bw4[(t * 4 + mt) * 32 + lane];
                        a[mt][0] = v.x; a[mt][1] = v.y; a[mt][2] = v.z; a[mt][3] = v.w;
                    }
                    const uint32_t* xp = bxu + ri * 1088 + xoff + kw;
                    #pragma unroll
                    for (int nt = 0; nt < 4; nt++) {
                        uint32_t b0 = xp[nt * 8];              // ci2 = lq
                        uint32_t b1 = xp[4 * 136 + nt * 8];    // ci2 = lq + 4
                        #pragma unroll
                        for (int mt = 0; mt < 4; mt++)
                            mma16(d[mt][nt], a[mt], b0, b1);
                    }
                }
            }

            if (cb < 3) {
                STSX(buf ^ 1);
                asm volatile("cp.async.wait_group 0;" ::: "memory");
                __syncthreads();
            }
        }

        // epilogue: store (bias already folded into d)
        int h = h0 + hl;
        #pragma unroll
        for (int mt = 0; mt < 4; mt++) {
            int co = mt * 16 + lr;
            float* r0 = out + (((size_t)(b * CO + co) * HHH + h) * WWW);
            float* r1 = out + (((size_t)(b * CO + co + 8) * HHH + h) * WWW);
            #pragma unroll
            for (int nt = 0; nt < 4; nt++) {
                int col = colb + nt * 8 + 2 * lq;
                *(float2*)(r0 + col) = make_float2(d[mt][nt][0], d[mt][nt][1]);
                *(float2*)(r1 + col) = make_float2(d[mt][nt][2], d[mt][nt][3]);
            }
        }
        // no barrier needed: next tile's prologue writes buffers 0 only and
        // publishes them with its own __syncthreads.
    }
}

// ---------------------------------------------------------------------------
extern "C" void kernel_launch(void* const* d_in, const int* in_sizes, int n_in,
                              void* d_out, int out_size) {
    const float* x      = (const float*)d_in[0];   // [16,64,128,128]
    const float* cond   = (const float*)d_in[1];   // [16,64]
    const float* filt_w = (const float*)d_in[2];   // [8,64,64,3,3]
    const float* filt_b = (const float*)d_in[3];   // [8,64]
    const float* sel_w  = (const float*)d_in[4];   // [8,64]
    const float* sel_b  = (const float*)d_in[5];   // [8]
    float* out = (float*)d_out;                    // [16,64,128,128]

    cudaFuncSetAttribute(k_conv, cudaFuncAttributeMaxDynamicSharedMemorySize, SMEM_BYTES);

    int nsm = 148;
    cudaDeviceGetAttribute(&nsm, cudaDevAttrMultiProcessorCount, 0);

    dim3 g1(16, BB);                               // 128 warp-tasks / 8 per block
    k_weff<<<g1, 256>>>(filt_w, cond, sel_w, sel_b, filt_b);

    int g2 = 2 * nsm;                              // persistent: 2 CTAs per SM
    if (g2 > NTILES) g2 = NTILES;
    k_conv<<<g2, 256, SMEM_BYTES>>>(x, out);
}